// round 6
// baseline (speedup 1.0000x reference)
#include <cuda_runtime.h>

// LocallyConnectedLinear: out[b,h,w,o] = sum_k xpatch[b,h,w,k] * W[h,w,k,o]
// x:  [8, 32, 32, 64]  f32   (NHWC)
// W:  [30, 30, 576, 64] f32  (k = c*9 + kh*3 + kw ; C slowest)
// out:[8, 30, 30, 64]  f32
//
// HBM-bound on the 132.7 MB weight stream (floor ~17us @ 8TB/s).
// R1 53.7us: 8x duplicated weight reads (L1-bound).
// R2 31.2us: unique weight reads, scalar FFMA, 24 warps/SM. DRAM 58%.
// R3 39.4us / R5 33.5us: FFMA2 variants — neutral/worse. Issue-slot theory
//     falsified: dur invariant under big instruction-mix changes.
// R4 33.3us: o-split + interleaved k. Same ceiling.
// Diagnosis: latency/MLP-bound. regs=80 capped occupancy at 24 warps/SM;
//     not enough outstanding LDGs to cover DRAM latency (DRAM idle 45%).
// R6: split batch over 2 threads (acc 16 regs), 256 thr/CTA,
//     __launch_bounds__(256,4) -> 32 warps/SM, unroll 6. Weight dedup via
//     intra-warp coalescing (bh lanes share addresses).

#define H_OUT 30
#define W_OUT 30
#define H_IN  32
#define W_IN  32
#define C_IN  64
#define C_OUT 64
#define KK    576   // 64 * 3 * 3
#define BATCH 8
#define NTHREADS 256
#define NSLICE 16   // interleaved: slice s owns k == s (mod 16)
#define KPS    36   // KK / NSLICE
#define NO4    8    // float4 output groups per CTA (32 of 64 channels)

__device__ __forceinline__ void fma4(float4& a, float s, const float4& w) {
    a.x += s * w.x; a.y += s * w.y; a.z += s * w.z; a.w += s * w.w;
}

__global__ __launch_bounds__(NTHREADS, 4)
void lc_kernel(const float* __restrict__ x,
               const float* __restrict__ w,
               float* __restrict__ out)
{
    // Phase 1: xs[k][b], KK x 8 floats = 18432 B.
    // Phase 2 (aliased): red[64 rows][17 float4] = 17408 B.
    __shared__ __align__(16) float smem[KK * BATCH];

    const int bid = blockIdx.x;          // 0..1799
    const int loc = bid >> 1;            // 0..899
    const int oh  = bid & 1;             // channel half: [oh*32, oh*32+32)
    const int h   = loc / W_OUT;
    const int wo  = loc - h * W_OUT;
    const int tid = threadIdx.x;

    // ---- Stage im2col patch: xs[k][b], k = c*9 + kh*3 + kw (c fastest) ----
    #pragma unroll
    for (int idx = tid; idx < BATCH * KK; idx += NTHREADS) {
        const int b   = idx / KK;
        const int r   = idx - b * KK;     // r = (kh*3+kw)*64 + c
        const int khw = r >> 6;           // kh*3 + kw
        const int c   = r & 63;
        const int kh  = khw / 3;
        const int kw  = khw - kh * 3;
        const int k   = c * 9 + khw;
        smem[k * BATCH + b] =
            x[(((b * H_IN) + h + kh) * W_IN + (wo + kw)) * C_IN + c];
    }
    __syncthreads();

    // ---- Main loop: thread = (ks, bh, o4). slice ks owns k = ks + 16j.
    // Warp = 2 ks x 2 bh x 8 o4:
    //   LDG: bh lanes share addresses (coalescer dedup); 2 x 128B half-rows.
    //   LDS: 4 distinct 16B chunks + broadcast -> conflict-free.
    const int o4 = tid & 7;           // 0..7  -> float4 group in half
    const int bh = (tid >> 3) & 1;    // 0..1  -> batch half (b = bh*4 .. +3)
    const int ks = tid >> 4;          // 0..15 -> k slice
    const float4* __restrict__ Wp =
        (const float4*)(w + (size_t)loc * (KK * C_OUT)) + oh * 8 + o4;  // [KK][16]

    float4 acc[4];
    #pragma unroll
    for (int i = 0; i < 4; ++i) acc[i] = make_float4(0.f, 0.f, 0.f, 0.f);

    #pragma unroll 6
    for (int j = 0; j < KPS; ++j) {
        const int k = ks + j * NSLICE;
        const float4 wv = __ldcs(Wp + k * (C_OUT / 4));                 // LDG.128
        const float4 xq = *(const float4*)(smem + k * BATCH + bh * 4);  // LDS.128
        fma4(acc[0], xq.x, wv);
        fma4(acc[1], xq.y, wv);
        fma4(acc[2], xq.z, wv);
        fma4(acc[3], xq.w, wv);
    }

    // ---- Reduce 16 k-slices through smem (aliased) ----
    __syncthreads();   // everyone done reading xs
    float4* red = (float4*)smem;   // [64 rows = b*8+o4][17]
    #pragma unroll
    for (int i = 0; i < 4; ++i) {
        const int b = bh * 4 + i;
        red[(b * NO4 + o4) * 17 + ks] = acc[i];
    }
    __syncthreads();

    if (tid < 64) {                       // one row (= one output float4) each
        const int row = tid;              // row = b*8 + o4f
        const int b   = row >> 3;
        const int o4f = row & 7;
        float4 s = red[row * 17];
        #pragma unroll
        for (int sl = 1; sl < NSLICE; ++sl) {
            const float4 p = red[row * 17 + sl];
            s.x += p.x; s.y += p.y; s.z += p.z; s.w += p.w;
        }
        float4* __restrict__ op =
            (float4*)(out + ((((size_t)b * H_OUT) + h) * W_OUT + wo) * C_OUT)
            + oh * 8 + o4f;
        *op = s;
    }
}

extern "C" void kernel_launch(void* const* d_in, const int* in_sizes, int n_in,
                              void* d_out, int out_size)
{
    const float* x  = (const float*)d_in[0];   // [8,32,32,64]
    const float* w  = (const float*)d_in[1];   // [30,30,576,64]
    float*       o  = (float*)d_out;           // [8,30,30,64]
    (void)in_sizes; (void)n_in; (void)out_size;

    lc_kernel<<<H_OUT * W_OUT * 2, NTHREADS>>>(x, w, o);
}

// round 7
// speedup vs baseline: 1.1837x; 1.1837x over previous
#include <cuda_runtime.h>
#include <cstdint>

// LocallyConnectedLinear: out[b,h,w,o] = sum_k xpatch[b,h,w,k] * W[h,w,k,o]
// x:  [8, 32, 32, 64]  f32 (NHWC)   W: [30, 30, 576, 64] f32 (k = c*9+kh*3+kw)
// out:[8, 30, 30, 64]  f32
//
// HBM-bound on the 132.7 MB weight stream (floor ~17us @ 8TB/s).
// R1 53.7 / R2 31.2 / R3 39.4 / R4 33.3 / R5 33.5 / R6 39.4:
//   every LDG-based variant pins DRAM at 46-58% regardless of mix/occupancy.
// R7: decouple the stream — cp.async.bulk (DMA) pipelines weight chunks into
//   smem (depth 3 x 12KB), compute is LDS + FFMA2 only. DMA keeps 36KB/CTA in
//   flight independent of warp scheduling.

#define H_OUT 30
#define W_OUT 30
#define H_IN  32
#define W_IN  32
#define C_IN  64
#define C_OUT 64
#define KK    576
#define BATCH 8
#define NTHREADS 128
#define NSLICE 8          // ks = tid>>4, owns rows ks+8i within each chunk
#define CHUNK_ROWS 48
#define NCHUNK 12         // 12 * 48 = 576
#define DEPTH 3
#define CHUNK_BYTES (CHUNK_ROWS * C_OUT * 4)          // 12288
#define XDUP_BYTES  (KK * BATCH * 8)                  // 36864 (float2 dup)
#define WBUF_OFF    XDUP_BYTES
#define MBAR_OFF    (WBUF_OFF + DEPTH * CHUNK_BYTES)  // 73728
#define SMEM_DYN    (MBAR_OFF + 64)

typedef unsigned long long u64;

__device__ __forceinline__ u64 fma2(u64 a, u64 b, u64 c) {
    u64 d;
    asm("fma.rn.f32x2 %0, %1, %2, %3;" : "=l"(d) : "l"(a), "l"(b), "l"(c));
    return d;
}
__device__ __forceinline__ u64 add2(u64 a, u64 b) {
    u64 d;
    asm("add.rn.f32x2 %0, %1, %2;" : "=l"(d) : "l"(a), "l"(b));
    return d;
}
__device__ __forceinline__ uint32_t smem_u32(const void* p) {
    uint32_t a;
    asm("{ .reg .u64 t; cvta.to.shared.u64 t, %1; cvt.u32.u64 %0, t; }"
        : "=r"(a) : "l"(p));
    return a;
}
__device__ __forceinline__ void mbar_init(uint32_t mbar, uint32_t cnt) {
    asm volatile("mbarrier.init.shared.b64 [%0], %1;" :: "r"(mbar), "r"(cnt) : "memory");
}
__device__ __forceinline__ void mbar_expect_tx(uint32_t mbar, uint32_t bytes) {
    asm volatile("mbarrier.arrive.expect_tx.shared.b64 _, [%0], %1;"
                 :: "r"(mbar), "r"(bytes) : "memory");
}
__device__ __forceinline__ void mbar_wait(uint32_t mbar, uint32_t parity) {
    asm volatile(
        "{\n\t.reg .pred P;\n"
        "W%=:\n\t"
        "mbarrier.try_wait.parity.acquire.cta.shared::cta.b64 P, [%0], %1, 0x989680;\n\t"
        "@P bra D%=;\n\t"
        "bra W%=;\n"
        "D%=:\n\t}"
        :: "r"(mbar), "r"(parity) : "memory");
}
__device__ __forceinline__ void bulk_ld(uint32_t dst, const void* src,
                                        uint32_t bytes, uint32_t mbar) {
    asm volatile(
        "cp.async.bulk.shared::cluster.global.mbarrier::complete_tx::bytes "
        "[%0], [%1], %2, [%3];"
        :: "r"(dst), "l"(src), "r"(bytes), "r"(mbar) : "memory");
}

__global__ __launch_bounds__(NTHREADS, 3)
void lc_kernel(const float* __restrict__ x,
               const float* __restrict__ w,
               float* __restrict__ out)
{
    extern __shared__ __align__(128) char sm[];
    u64*   xdup  = (u64*)sm;                         // [KK][8] dup'd pairs
    float* wbuf  = (float*)(sm + WBUF_OFF);          // [DEPTH][48*64]
    const uint32_t wbuf_u32 = smem_u32(wbuf);
    const uint32_t mbar0    = smem_u32(sm + MBAR_OFF);

    const int loc = blockIdx.x;          // 0..899
    const int h   = loc / W_OUT;
    const int wo  = loc - h * W_OUT;
    const int tid = threadIdx.x;

    if (tid == 0) {
        #pragma unroll
        for (int s = 0; s < DEPTH; ++s) mbar_init(mbar0 + s * 8, 1);
    }

    // ---- Stage x duplicated: xdup[k*8+b] = (v,v); k = c*9+kh*3+kw ----
    #pragma unroll
    for (int idx = tid; idx < BATCH * KK; idx += NTHREADS) {
        const int b   = idx / KK;
        const int r   = idx - b * KK;     // (kh*3+kw)*64 + c  (c fastest)
        const int khw = r >> 6;
        const int c   = r & 63;
        const int kh  = khw / 3;
        const int kw  = khw - kh * 3;
        const int k   = c * 9 + khw;
        const float v = x[(((b * H_IN) + h + kh) * W_IN + (wo + kw)) * C_IN + c];
        float2 d2 = make_float2(v, v);
        xdup[k * BATCH + b] = *(const u64*)&d2;
    }
    __syncthreads();   // x staged + mbarriers visible

    const float* __restrict__ wloc = w + (size_t)loc * (KK * C_OUT);

    // ---- Prologue: fill the pipeline ----
    if (tid == 0) {
        #pragma unroll
        for (int c = 0; c < DEPTH; ++c) {
            mbar_expect_tx(mbar0 + c * 8, CHUNK_BYTES);
            bulk_ld(wbuf_u32 + c * CHUNK_BYTES,
                    wloc + (size_t)c * (CHUNK_ROWS * C_OUT),
                    CHUNK_BYTES, mbar0 + c * 8);
        }
    }

    const int o4 = tid & 15;    // float4 group (o channels o4*4..+3)
    const int ks = tid >> 4;    // 0..7, owns local rows ks + 8i

    u64 acc01[BATCH], acc23[BATCH];
    #pragma unroll
    for (int b = 0; b < BATCH; ++b) { acc01[b] = 0ull; acc23[b] = 0ull; }

    for (int c = 0; c < NCHUNK; ++c) {
        const int s = c % DEPTH;
        mbar_wait(mbar0 + s * 8, (c / DEPTH) & 1);

        const float* __restrict__ wc = wbuf + s * (CHUNK_ROWS * C_OUT);
        #pragma unroll
        for (int i = 0; i < CHUNK_ROWS / NSLICE; ++i) {   // 6 rows per thread
            const int row = ks + i * NSLICE;
            // phase (8 lanes, same ks) reads one 128B row segment: conflict-free
            const float4 wv = *(const float4*)(wc + row * C_OUT + o4 * 4);
            const u64 w01 = ((const u64*)&wv)[0];
            const u64 w23 = ((const u64*)&wv)[1];
            const u64* xp = xdup + (c * CHUNK_ROWS + row) * BATCH; // broadcast
            #pragma unroll
            for (int b = 0; b < BATCH; ++b) {
                const u64 xb = xp[b];
                acc01[b] = fma2(xb, w01, acc01[b]);
                acc23[b] = fma2(xb, w23, acc23[b]);
            }
        }
        __syncthreads();   // all warps done with stage s
        if (tid == 0 && c + DEPTH < NCHUNK) {
            mbar_expect_tx(mbar0 + s * 8, CHUNK_BYTES);
            bulk_ld(wbuf_u32 + s * CHUNK_BYTES,
                    wloc + (size_t)(c + DEPTH) * (CHUNK_ROWS * C_OUT),
                    CHUNK_BYTES, mbar0 + s * 8);
        }
    }

    // ---- Reduce 8 k-slices through smem (alias wbuf region; all TMA done) ----
    ulonglong2* red = (ulonglong2*)wbuf;   // [8][16][9] = 18KB <= 36KB
    #pragma unroll
    for (int b = 0; b < BATCH; ++b)
        red[(ks * 16 + o4) * 9 + b] = make_ulonglong2(acc01[b], acc23[b]);
    __syncthreads();

    {
        const int b = tid >> 4;   // 0..7
        ulonglong2 sv = red[o4 * 9 + b];
        #pragma unroll
        for (int sl = 1; sl < NSLICE; ++sl) {
            const ulonglong2 p = red[(sl * 16 + o4) * 9 + b];
            sv.x = add2(sv.x, p.x);
            sv.y = add2(sv.y, p.y);
        }
        ulonglong2* __restrict__ op =
            (ulonglong2*)(out + ((((size_t)b * H_OUT) + h) * W_OUT + wo) * C_OUT);
        op[o4] = sv;
    }
}

extern "C" void kernel_launch(void* const* d_in, const int* in_sizes, int n_in,
                              void* d_out, int out_size)
{
    const float* x  = (const float*)d_in[0];   // [8,32,32,64]
    const float* w  = (const float*)d_in[1];   // [30,30,576,64]
    float*       o  = (float*)d_out;           // [8,30,30,64]
    (void)in_sizes; (void)n_in; (void)out_size;

    cudaFuncSetAttribute(lc_kernel, cudaFuncAttributeMaxDynamicSharedMemorySize,
                         SMEM_DYN);
    lc_kernel<<<H_OUT * W_OUT, NTHREADS, SMEM_DYN>>>(x, w, o);
}